// round 5
// baseline (speedup 1.0000x reference)
#include <cuda_runtime.h>
#include <math.h>

// DDSL spec: B=2, NV=NE=512, RES=(128,128) -> freq grid 128 x 65, J=2.
// out: (B, 128, 65, 1, 2) float32.
// Ring connectivity: edge e = (e, e+1 mod NV); t1(edge e) == t0(edge e+1).
// Two adjacent fx frequencies (kx, kx+1) packed per thread via f32x2 (FFMA2).
// One full warp per freq-pair (32 edge-chunk lanes of 16 edges) for occupancy.

#define NV      512
#define NE      512
#define FX      128
#define FY2     65
#define NFP     (FX / 2 * FY2)      // 4160 fx-pairs
#define LANES   32                  // edge-chunk lanes per freq-pair (full warp)
#define GROUPS  8                   // freq-pairs (warps) per block
#define BLOCK   256
#define EPL     16                  // edges per lane
#define PADDED  529                 // pad(e)=e+(e>>5), holds pad(512)=528

typedef unsigned long long u64;

__device__ __forceinline__ u64 pk2(float a, float b) {
    u64 r; asm("mov.b64 %0, {%1, %2};" : "=l"(r) : "f"(a), "f"(b)); return r;
}
__device__ __forceinline__ void upk(u64 v, float& a, float& b) {
    asm("mov.b64 {%0, %1}, %2;" : "=f"(a), "=f"(b) : "l"(v));
}
__device__ __forceinline__ u64 f2fma(u64 a, u64 b, u64 c) {
    u64 d; asm("fma.rn.f32x2 %0, %1, %2, %3;" : "=l"(d) : "l"(a), "l"(b), "l"(c)); return d;
}
__device__ __forceinline__ u64 f2add(u64 a, u64 b) {
    u64 d; asm("add.rn.f32x2 %0, %1, %2;" : "=l"(d) : "l"(a), "l"(b)); return d;
}
__device__ __forceinline__ u64 f2mul(u64 a, u64 b) {
    u64 d; asm("mul.rn.f32x2 %0, %1, %2;" : "=l"(d) : "l"(a), "l"(b)); return d;
}

__global__ __launch_bounds__(BLOCK)
void ddsl_spec_kernel(const float* __restrict__ V,
                      const int*   __restrict__ E,
                      const float* __restrict__ D,
                      float*       __restrict__ out)
{
    __shared__ float sX[PADDED];    // x of ring vertex e (first endpoint of edge e)
    __shared__ float sY[PADDED];
    __shared__ float sCD[PADDED];   // C * D per edge

    const int b = blockIdx.y;

    // ---- setup: stage first endpoints + C*D (C from actual E gather) ----
    for (int e = threadIdx.x; e < NE; e += BLOCK) {
        int i0 = E[(b * NE + e) * 2 + 0];
        int i1 = E[(b * NE + e) * 2 + 1];
        float x0 = V[(b * NV + i0) * 2 + 0];
        float y0 = V[(b * NV + i0) * 2 + 1];
        float x1 = V[(b * NV + i1) * 2 + 0];
        float y1 = V[(b * NV + i1) * 2 + 1];
        int p = e + (e >> 5);
        sX[p] = x0;
        sY[p] = y0;
        float C = x0 * y1 - y0 * x1;   // signed 2*area, third vertex = origin
        sCD[p] = C * D[b * NE + e];
        if (e == 0) {                  // ring-wrap duplicate at pad(512)=528
            sX[528] = x0;
            sY[528] = y0;
        }
    }
    __syncthreads();

    const int lane = threadIdx.x & 31;
    const int fp   = blockIdx.x * GROUPS + (threadIdx.x >> 5);  // fx-pair index

    const int fxp = fp / FY2;            // 0..63
    const int fy  = fp - fxp * FY2;
    const int fx0 = 2 * fxp;
    const int kx0 = (fx0 < FX / 2) ? fx0 : fx0 - FX;   // kx1 = kx0 + 1 always
    const float fkx = (float)kx0;
    const float fky = (float)fy;

    const float TWO_PI = 6.28318530717958647692f;
    const float MAGIC  = 12582912.0f;   // 1.5 * 2^23
    const u64 MAGIC2  = pk2(MAGIC, MAGIC);
    const u64 NMAGIC2 = pk2(-MAGIC, -MAGIC);
    const u64 NEG1    = pk2(-1.0f, -1.0f);
    const u64 TWOPI2  = pk2(TWO_PI, TWO_PI);

    // lane's 16-edge chunk lives inside one pad-group:
    // pad(16*lane + i) = 16*lane + (lane>>1) + i  for i = 0..15
    // the ring-next of the last edge crosses a group boundary iff lane is odd.
    const int base = 16 * lane + (lane >> 1);
    const float* xb = &sX[base];
    const float* yb = &sY[base];
    const float* cb = &sCD[base];
    const int lastoff = 16 + (lane & 1);

    u64 accR = pk2(0.0f, 0.0f);
    u64 accI = pk2(0.0f, 0.0f);   // accumulates -Im (sign folded at output)

    // first vertex of this chunk
    float vx0 = xb[0], vy0 = yb[0];
    float tlo = fmaf(vy0, fky, vx0 * fkx);
    u64 t0 = pk2(tlo, tlo + vx0);
    u64 sn0, cs0;
    {
        u64 g = f2add(t0, MAGIC2);
        u64 r = f2add(g, NMAGIC2);
        u64 u = f2fma(r, NEG1, t0);
        u64 ph = f2mul(u, TWOPI2);
        float plo, phi, sl, cl, sh, ch;
        upk(ph, plo, phi);
        __sincosf(plo, &sl, &cl);
        __sincosf(phi, &sh, &ch);
        sn0 = pk2(sl, sh); cs0 = pk2(cl, ch);
    }

#pragma unroll
    for (int i = 0; i < EPL; ++i) {
        const int off = (i == EPL - 1) ? lastoff : (i + 1);
        float nx = xb[off];
        float ny = yb[off];
        float cd = cb[i];

        float t1lo = fmaf(ny, fky, nx * fkx);
        u64 t1 = pk2(t1lo, t1lo + nx);              // kx+1 adds exactly x

        // packed round_frac + 2*pi
        u64 g  = f2add(t1, MAGIC2);
        u64 r  = f2add(g, NMAGIC2);
        u64 u  = f2fma(r, NEG1, t1);
        u64 ph = f2mul(u, TWOPI2);
        float plo, phi, sl, cl, sh, ch;
        upk(ph, plo, phi);
        __sincosf(plo, &sl, &cl);
        __sincosf(phi, &sh, &ch);
        u64 sn1 = pk2(sl, sh), cs1 = pk2(cl, ch);

        u64 dt    = f2fma(t1, NEG1, t0);            // t0 - t1
        u64 denom = f2mul(f2mul(t0, t1), dt);
        u64 nt0   = f2mul(t0, NEG1);

        // numR = dt + cs0*t1 - cs1*t0 ; numI2 = sn0*t1 - sn1*t0 = -numI
        u64 numR  = f2fma(cs1, nt0, f2fma(cs0, t1, dt));
        u64 numI2 = f2fma(sn1, nt0, f2mul(sn0, t1));

        float dlo, dhi;
        upk(denom, dlo, dhi);
        float rlo = (dlo != 0.0f) ? __fdividef(cd, dlo) : 0.0f;
        float rhi = (dhi != 0.0f) ? __fdividef(cd, dhi) : 0.0f;
        u64 rc = pk2(rlo, rhi);

        accR = f2fma(numR,  rc, accR);
        accI = f2fma(numI2, rc, accI);

        t0 = t1; sn0 = sn1; cs0 = cs1;              // ring reuse
    }

    // ---- reduce the 32 edge-chunk lanes (packed) ----
#pragma unroll
    for (int off = 16; off > 0; off >>= 1) {
        u64 oR = __shfl_down_sync(0xFFFFFFFFu, accR, off);
        u64 oI = __shfl_down_sync(0xFFFFFFFFu, accI, off);
        accR = f2add(accR, oR);
        accI = f2add(accI, oI);
    }

    if (lane == 0) {
        // F = -einsum * RES^J ; tmp carried a (2*pi)^-2 we folded out.
        // accI holds -Im, so its output scale flips sign.
        const float SCALE = (float)(-16384.0 / (4.0 * 3.14159265358979323846
                                                    * 3.14159265358979323846));
        float aRlo, aRhi, aIlo, aIhi;
        upk(accR, aRlo, aRhi);
        upk(accI, aIlo, aIhi);
        float oRlo = SCALE * aRlo, oRhi = SCALE * aRhi;
        float oIlo = -SCALE * aIlo, oIhi = -SCALE * aIhi;

        if (fp == 0) {
            // DC at (fx=0, fy=0) = lo element of pair 0:
            // F[:,0,0,:,:] = 8192 * sum(C*D), broadcast into re AND im.
            float s = 0.0f;
#pragma unroll 8
            for (int e = 0; e < NE; ++e) s += sCD[e + (e >> 5)];
            oRlo = 8192.0f * s;
            oIlo = oRlo;
        }

        int basei = ((b * FX + fx0) * FY2 + fy) * 2;
        out[basei + 0] = oRlo;
        out[basei + 1] = oIlo;
        out[basei + FY2 * 2 + 0] = oRhi;   // fx0 + 1
        out[basei + FY2 * 2 + 1] = oIhi;
    }
}

extern "C" void kernel_launch(void* const* d_in, const int* in_sizes, int n_in,
                              void* d_out, int out_size)
{
    const float* V = (const float*)d_in[0];
    const int*   E = (const int*)  d_in[1];
    const float* D = (const float*)d_in[2];
    float* out = (float*)d_out;

    const int B = in_sizes[0] / (NV * 2);   // 2
    dim3 grid(NFP / GROUPS, B);             // (520, 2) = 1040 blocks
    ddsl_spec_kernel<<<grid, BLOCK>>>(V, E, D, out);
}